// round 3
// baseline (speedup 1.0000x reference)
#include <cuda_runtime.h>
#include <math.h>

// Shapes: T_FAST=512, T_SLOW=128, B=32, D=1024, H=256
// Inputs (metadata order):
// 0..3: feat0..feat3 [T,B,D] fp32
// 4: mlp_w1 [16,2048,256]  5: mlp_b1 [16,256]
// 6: mlp_w2 [16,256,1]     7: mlp_b2 [16,1]
// 8: s2f_w [1024,1024,1]   9: s2f_b [1024]
// 10: f2s_w [4,1024,1024,5]
// Output: concat(out0[512,32,1024], out1, out2[128,32,1024], out3) fp32

#define BATCH 32
#define DDIM  1024

// ---------------- scratch (device globals; no allocation allowed) ----------------
static __device__ float g_means[4][BATCH][DDIM];          // 512 KB
static __device__ float g_score[16][BATCH];
static __device__ float g_selscore[4][BATCH];
static __device__ int   g_sel[4];                          // selected source per output slot, -1 = none
static __device__ float g_y[2][128 * BATCH * DDIM];        // s2f conv output at slow res, 33.5 MB
static __device__ float g_wT[2][5][DDIM][DDIM];            // repacked f2s weights [slot][tap][dout][din], 42 MB

__constant__ int c_api[8] = {2, 2, 3, 3, 0, 0, 1, 1};
__constant__ int c_apj[8] = {0, 1, 0, 1, 2, 3, 2, 3};

// ---------------- packed fp32x2 helpers (sm_100+) ----------------
__device__ __forceinline__ unsigned long long pack_dup(float x) {
    unsigned long long r; asm("mov.b64 %0, {%1, %1};" : "=l"(r) : "f"(x)); return r;
}
__device__ __forceinline__ unsigned long long pack_pair(float lo, float hi) {
    unsigned long long r; asm("mov.b64 %0, {%1, %2};" : "=l"(r) : "f"(lo), "f"(hi)); return r;
}
__device__ __forceinline__ void fma2(unsigned long long& d, unsigned long long a, unsigned long long b) {
    asm("fma.rn.f32x2 %0, %1, %2, %0;" : "+l"(d) : "l"(a), "l"(b));
}
__device__ __forceinline__ void unpack_pair(unsigned long long v, float& lo, float& hi) {
    asm("mov.b64 {%0, %1}, %2;" : "=f"(lo), "=f"(hi) : "l"(v));
}

// ---------------- 1) per-stream global means over T ----------------
__global__ void means_kernel(const float* __restrict__ f0, const float* __restrict__ f1,
                             const float* __restrict__ f2, const float* __restrict__ f3) {
    int z = blockIdx.y;
    const float* f = (z == 0) ? f0 : (z == 1) ? f1 : (z == 2) ? f2 : f3;
    int T = (z < 2) ? 512 : 128;
    int idx = blockIdx.x * blockDim.x + threadIdx.x;   // 0 .. 32767 (b*1024+d)
    if (idx >= BATCH * DDIM) return;
    float s0 = 0.f, s1 = 0.f, s2 = 0.f, s3 = 0.f;
    const float* p = f + idx;
    const int STRIDE = BATCH * DDIM;
    #pragma unroll 4
    for (int t = 0; t < T; t += 4) {
        s0 += p[(size_t)(t + 0) * STRIDE];
        s1 += p[(size_t)(t + 1) * STRIDE];
        s2 += p[(size_t)(t + 2) * STRIDE];
        s3 += p[(size_t)(t + 3) * STRIDE];
    }
    (&g_means[z][0][0])[idx] = ((s0 + s1) + (s2 + s3)) * (1.0f / (float)T);
}

// ---------------- 2) pair-gate MLPs (8 active pairs) ----------------
__global__ void mlp_kernel(const float* __restrict__ w1, const float* __restrict__ b1,
                           const float* __restrict__ w2, const float* __restrict__ b2) {
    __shared__ float vec[4][2048];
    __shared__ float red[4][256];
    int pi = blockIdx.x, bg = blockIdx.y;
    int i = c_api[pi], j = c_apj[pi];
    int p = i * 4 + j;
    int tid = threadIdx.x;
    for (int q = 0; q < 4; ++q) {
        int b = bg * 4 + q;
        for (int k = tid; k < 2048; k += 256)
            vec[q][k] = (k < 1024) ? g_means[i][b][k] : g_means[j][b][k - 1024];
    }
    __syncthreads();
    const float* w1p = w1 + (size_t)p * 2048 * 256 + tid;
    float a0 = 0.f, a1 = 0.f, a2 = 0.f, a3 = 0.f;
    #pragma unroll 4
    for (int k = 0; k < 2048; ++k) {
        float w = w1p[(size_t)k * 256];
        a0 = fmaf(vec[0][k], w, a0);
        a1 = fmaf(vec[1][k], w, a1);
        a2 = fmaf(vec[2][k], w, a2);
        a3 = fmaf(vec[3][k], w, a3);
    }
    float bb = b1[p * 256 + tid];
    float wv = w2[p * 256 + tid];
    red[0][tid] = fmaxf(a0 + bb, 0.f) * wv;
    red[1][tid] = fmaxf(a1 + bb, 0.f) * wv;
    red[2][tid] = fmaxf(a2 + bb, 0.f) * wv;
    red[3][tid] = fmaxf(a3 + bb, 0.f) * wv;
    __syncthreads();
    for (int s = 128; s > 0; s >>= 1) {
        if (tid < s) {
            red[0][tid] += red[0][tid + s];
            red[1][tid] += red[1][tid + s];
            red[2][tid] += red[2][tid + s];
            red[3][tid] += red[3][tid + s];
        }
        __syncthreads();
    }
    if (tid < 4) {
        float z = red[tid][0] + b2[p];
        g_score[p][bg * 4 + tid] = 1.f / (1.f + expf(-z));
    }
}

// ---------------- 3) resolve where(cond,...) chains to one source per slot ----------------
__global__ void select_kernel() {
    int j = threadIdx.x >> 5;          // output slot 0..3
    int lane = threadIdx.x & 31;       // batch index
    int pA, pB, iA, iB;
    if (j < 2) { pA = 12 + j; iA = 3; pB = 8 + j; iB = 2; }   // slow->fast: i=3 overwrites i=2
    else       { pA = 4 + j;  iA = 1; pB = j;     iB = 0; }   // fast->slow: i=1 overwrites i=0
    float sA = g_score[pA][lane], sB = g_score[pB][lane];
    float mA = sA, mB = sB;
    #pragma unroll
    for (int o = 16; o > 0; o >>= 1) {
        mA += __shfl_xor_sync(0xffffffffu, mA, o);
        mB += __shfl_xor_sync(0xffffffffu, mB, o);
    }
    bool cA = (mA * (1.f / 32.f)) >= 0.3f;
    bool cB = (mB * (1.f / 32.f)) >= 0.3f;
    int sel = cA ? iA : (cB ? iB : -1);
    g_selscore[j][lane] = cA ? sA : (cB ? sB : 0.f);
    if (lane == 0) g_sel[j] = sel;
}

// ---------------- 4) repack selected f2s weights [dout][din][k] -> [tap][dout][din] ----------------
__global__ void repack_kernel(const float* __restrict__ f2s_w) {
    long long idx = (long long)blockIdx.x * blockDim.x + threadIdx.x;
    const long long per_slot = 5LL * 1024 * 1024;
    if (idx >= 2 * per_slot) return;
    int slot = (int)(idx / per_slot);            // slot 0 -> out2, 1 -> out3
    int sel = g_sel[slot + 2];
    if (sel < 0) return;
    int widx = sel * 2 + slot;                   // F2S_IDX[(i, j)] = i*2 + (j-2)
    long long r = idx - (long long)slot * per_slot;
    int tap = (int)(r >> 20);
    int rr = (int)(r & 1048575);
    int dout = rr >> 10, din = rr & 1023;
    g_wT[slot][tap][dout][din] =
        f2s_w[(((long long)widx * 1024 + dout) * 1024 + din) * 5 + tap];
}

// ---------------- shared SGEMM inner step (128x128 tile, BK=8, 8x8/thread, fp32x2) -------------
__device__ __forceinline__ void mma_step(const float* __restrict__ Xs, const float* __restrict__ Ws,
                                         int ty, int tx, unsigned long long (&acc)[8][4]) {
    #pragma unroll
    for (int k = 0; k < 8; ++k) {
        float4 xa = *(const float4*)(Xs + k * 128 + ty * 8);
        float4 xb = *(const float4*)(Xs + k * 128 + ty * 8 + 4);
        float4 w0 = *(const float4*)(Ws + k * 128 + tx * 8);
        float4 w1 = *(const float4*)(Ws + k * 128 + tx * 8 + 4);
        unsigned long long wv[4];
        wv[0] = pack_pair(w0.x, w0.y); wv[1] = pack_pair(w0.z, w0.w);
        wv[2] = pack_pair(w1.x, w1.y); wv[3] = pack_pair(w1.z, w1.w);
        float xr[8] = {xa.x, xa.y, xa.z, xa.w, xb.x, xb.y, xb.z, xb.w};
        #pragma unroll
        for (int i = 0; i < 8; ++i) {
            unsigned long long xx = pack_dup(xr[i]);
            #pragma unroll
            for (int jj = 0; jj < 4; ++jj) fma2(acc[i][jj], xx, wv[jj]);
        }
    }
}

// ---------------- 5) s2f 1x1-conv GEMM at slow resolution: y = W @ feat_sel + b -------------
__global__ __launch_bounds__(256, 2)
void s2f_gemm(const float* __restrict__ f2, const float* __restrict__ f3,
              const float* __restrict__ w, const float* __restrict__ bias) {
    int slot = blockIdx.z;                 // output slot 0 / 1 (fast streams)
    int sel = g_sel[slot];
    if (sel < 0) return;
    const float* X = (sel == 3) ? f3 : f2; // [4096][1024] row-major (n=(t,b), k=din)
    float* Y = g_y[slot];
    int m0 = blockIdx.x * 128, n0 = blockIdx.y * 128;
    __shared__ float Ws[8 * 128];
    __shared__ float Xs[8 * 128];
    int tid = threadIdx.x;
    int lrow = tid >> 1, lcol = (tid & 1) << 2;
    int tx = tid & 15, ty = tid >> 4;
    unsigned long long acc[8][4];
    #pragma unroll
    for (int i = 0; i < 8; ++i)
        #pragma unroll
        for (int jj = 0; jj < 4; ++jj) acc[i][jj] = 0ULL;
    const float* wp = w + (size_t)(m0 + lrow) * 1024 + lcol;
    const float* xp = X + (size_t)(n0 + lrow) * 1024 + lcol;
    for (int kt = 0; kt < 128; ++kt) {
        float4 wv4 = *(const float4*)(wp + kt * 8);
        float4 xv4 = *(const float4*)(xp + kt * 8);
        __syncthreads();
        Ws[(lcol + 0) * 128 + lrow] = wv4.x; Ws[(lcol + 1) * 128 + lrow] = wv4.y;
        Ws[(lcol + 2) * 128 + lrow] = wv4.z; Ws[(lcol + 3) * 128 + lrow] = wv4.w;
        Xs[(lcol + 0) * 128 + lrow] = xv4.x; Xs[(lcol + 1) * 128 + lrow] = xv4.y;
        Xs[(lcol + 2) * 128 + lrow] = xv4.z; Xs[(lcol + 3) * 128 + lrow] = xv4.w;
        __syncthreads();
        mma_step(Xs, Ws, ty, tx, acc);
    }
    int m = m0 + tx * 8;
    float bz[8];
    #pragma unroll
    for (int jj = 0; jj < 8; ++jj) bz[jj] = bias[m + jj];
    #pragma unroll
    for (int i = 0; i < 8; ++i) {
        int n = n0 + ty * 8 + i;
        float o[8];
        #pragma unroll
        for (int jj = 0; jj < 4; ++jj) unpack_pair(acc[i][jj], o[2 * jj], o[2 * jj + 1]);
        float4 r0 = make_float4(o[0] + bz[0], o[1] + bz[1], o[2] + bz[2], o[3] + bz[3]);
        float4 r1 = make_float4(o[4] + bz[4], o[5] + bz[5], o[6] + bz[6], o[7] + bz[7]);
        *(float4*)(Y + (size_t)n * 1024 + m) = r0;
        *(float4*)(Y + (size_t)n * 1024 + m + 4) = r1;
    }
}

// ---------------- 6) fast outputs: linear-interp upsample + gated residual -------------
__global__ void upsample_kernel(const float* __restrict__ f0, const float* __restrict__ f1,
                                float* __restrict__ out) {
    int slot = blockIdx.y;
    const float* FJ = slot ? f1 : f0;
    float* O = out + (size_t)slot * 16777216;
    int idx4 = blockIdx.x * blockDim.x + threadIdx.x;   // float4 units over [512][32][256]
    if (idx4 >= 512 * 32 * 256) return;
    float4 base = ((const float4*)FJ)[idx4];
    float4 res = base;
    int sel = g_sel[slot];
    if (sel >= 0) {
        int t = idx4 / (32 * 256);
        int rem = idx4 % (32 * 256);
        int b = rem >> 8;
        float s = g_selscore[slot][b];
        float srcp = (t + 0.5f) * 0.25f - 0.5f;
        srcp = fminf(fmaxf(srcp, 0.f), 127.f);
        int i0 = (int)floorf(srcp);
        int i1 = min(i0 + 1, 127);
        float wgt = srcp - (float)i0;
        const float4* yp = (const float4*)g_y[slot];
        float4 a = yp[i0 * (32 * 256) + rem];
        float4 c = yp[i1 * (32 * 256) + rem];
        res.x = base.x + s * ((1.f - wgt) * a.x + wgt * c.x);
        res.y = base.y + s * ((1.f - wgt) * a.y + wgt * c.y);
        res.z = base.z + s * ((1.f - wgt) * a.z + wgt * c.z);
        res.w = base.w + s * ((1.f - wgt) * a.w + wgt * c.w);
    }
    ((float4*)O)[idx4] = res;
}

// ---------------- 7) slow outputs: fused strided-conv GEMM + gated residual -------------
__global__ __launch_bounds__(256, 2)
void f2s_gemm(const float* __restrict__ f0, const float* __restrict__ f1,
              const float* __restrict__ f2, const float* __restrict__ f3,
              float* __restrict__ outbase) {
    int slot = blockIdx.z;                 // 0 -> out2, 1 -> out3
    int j = slot + 2;
    const float* FJ = (slot == 0) ? f2 : f3;
    float* O = outbase + ((slot == 0) ? (size_t)33554432 : (size_t)37748736);
    int m0 = blockIdx.x * 128, n0 = blockIdx.y * 128;
    int tid = threadIdx.x;
    int sel = g_sel[j];
    if (sel < 0) {                          // no gate fired: output = input copy
        int c = tid & 31;
        for (int r = tid >> 5; r < 128; r += 8) {
            size_t off = (size_t)(n0 + r) * 1024 + m0;
            ((float4*)(O + off))[c] = ((const float4*)(FJ + off))[c];
        }
        return;
    }
    const float* X = (sel == 1) ? f1 : f0;  // fast source [512][32][1024]
    __shared__ float Ws[8 * 128];
    __shared__ float Xs[8 * 128];
    int lrow = tid >> 1, lcol = (tid & 1) << 2;
    int tx = tid & 15, ty = tid >> 4;
    unsigned long long acc[8][4];
    #pragma unroll
    for (int i = 0; i < 8; ++i)
        #pragma unroll
        for (int jj = 0; jj < 4; ++jj) acc[i][jj] = 0ULL;
    int nl = n0 + lrow;
    int tL = nl >> 5, bL = nl & 31;
    const float* wbase = &g_wT[slot][0][m0 + lrow][lcol];
    for (int kt = 0; kt < 640; ++kt) {
        int tap = kt >> 7;
        int din0 = (kt & 127) << 3;
        float4 wv4 = *(const float4*)(wbase + (size_t)tap * 1024 * 1024 + din0);
        int time = 4 * tL - 2 + tap;        // stride 4, pad 2; max time = 510 < 512
        float4 xv4 = make_float4(0.f, 0.f, 0.f, 0.f);
        if (time >= 0)
            xv4 = *(const float4*)(X + ((size_t)time * 32 + bL) * 1024 + din0 + lcol);
        __syncthreads();
        Ws[(lcol + 0) * 128 + lrow] = wv4.x; Ws[(lcol + 1) * 128 + lrow] = wv4.y;
        Ws[(lcol + 2) * 128 + lrow] = wv4.z; Ws[(lcol + 3) * 128 + lrow] = wv4.w;
        Xs[(lcol + 0) * 128 + lrow] = xv4.x; Xs[(lcol + 1) * 128 + lrow] = xv4.y;
        Xs[(lcol + 2) * 128 + lrow] = xv4.z; Xs[(lcol + 3) * 128 + lrow] = xv4.w;
        __syncthreads();
        mma_step(Xs, Ws, ty, tx, acc);
    }
    int m = m0 + tx * 8;
    #pragma unroll
    for (int i = 0; i < 8; ++i) {
        int n = n0 + ty * 8 + i;
        float s = g_selscore[j][n & 31];
        float o[8];
        #pragma unroll
        for (int jj = 0; jj < 4; ++jj) unpack_pair(acc[i][jj], o[2 * jj], o[2 * jj + 1]);
        size_t off = (size_t)n * 1024 + m;
        float4 b0 = *(const float4*)(FJ + off);
        float4 b1 = *(const float4*)(FJ + off + 4);
        float4 r0 = make_float4(b0.x + s * o[0], b0.y + s * o[1], b0.z + s * o[2], b0.w + s * o[3]);
        float4 r1 = make_float4(b1.x + s * o[4], b1.y + s * o[5], b1.z + s * o[6], b1.w + s * o[7]);
        *(float4*)(O + off) = r0;
        *(float4*)(O + off + 4) = r1;
    }
}

// ---------------- launch ----------------
extern "C" void kernel_launch(void* const* d_in, const int* in_sizes, int n_in,
                              void* d_out, int out_size) {
    (void)in_sizes; (void)n_in; (void)out_size;
    const float* f0 = (const float*)d_in[0];
    const float* f1 = (const float*)d_in[1];
    const float* f2 = (const float*)d_in[2];
    const float* f3 = (const float*)d_in[3];
    const float* w1 = (const float*)d_in[4];
    const float* b1 = (const float*)d_in[5];
    const float* w2 = (const float*)d_in[6];
    const float* b2 = (const float*)d_in[7];
    const float* s2f_w = (const float*)d_in[8];
    const float* s2f_b = (const float*)d_in[9];
    const float* f2s_w = (const float*)d_in[10];
    float* out = (float*)d_out;

    means_kernel<<<dim3(128, 4), 256>>>(f0, f1, f2, f3);
    mlp_kernel<<<dim3(8, 8), 256>>>(w1, b1, w2, b2);
    select_kernel<<<1, 128>>>();
    repack_kernel<<<40960, 256>>>(f2s_w);
    s2f_gemm<<<dim3(8, 32, 2), 256>>>(f2, f3, s2f_w, s2f_b);
    upsample_kernel<<<dim3(16384, 2), 256>>>(f0, f1, out);
    f2s_gemm<<<dim3(8, 32, 2), 256>>>(f0, f1, f2, f3, out);
}

// round 4
// speedup vs baseline: 2.6583x; 2.6583x over previous
#include <cuda_runtime.h>
#include <math.h>
#include <stdint.h>

// Shapes: T_FAST=512, T_SLOW=128, B=32, D=1024, H=256
// Inputs (metadata order):
// 0..3: feat0..feat3 [T,B,D] fp32
// 4: mlp_w1 [16,2048,256]  5: mlp_b1 [16,256]
// 6: mlp_w2 [16,256,1]     7: mlp_b2 [16,1]
// 8: s2f_w [1024,1024,1]   9: s2f_b [1024]
// 10: f2s_w [4,1024,1024,5]
// Output: concat(out0[512,32,1024], out1, out2[128,32,1024], out3) fp32

#define BATCH 32
#define DDIM  1024

// ---------------- scratch (device globals; no allocation allowed) ----------------
static __device__ float g_means[4][BATCH][DDIM];
static __device__ float g_score[16][BATCH];
static __device__ float g_selscore[4][BATCH];
static __device__ int   g_sel[4];
static __device__ __align__(128) float g_y[2][128 * BATCH * DDIM];      // s2f conv out, 33.5 MB
static __device__ __align__(128) float g_wT2[2][5120 * 1024];           // f2s W as [k][dout], tf32-rounded, 42 MB
static __device__ __align__(128) float g_s2fT[1024 * 1024];             // s2f W as [din][dout], tf32-rounded, 4 MB

__constant__ int c_api[8] = {2, 2, 3, 3, 0, 0, 1, 1};
__constant__ int c_apj[8] = {0, 1, 0, 1, 2, 3, 2, 3};

// ---------------- helpers ----------------
__device__ __forceinline__ float to_tf32(float x) {
    uint32_t u; asm("cvt.rna.tf32.f32 %0, %1;" : "=r"(u) : "f"(x));
    return __uint_as_float(u);
}
__device__ __forceinline__ uint32_t smem_u32(const void* p) {
    return (uint32_t)__cvta_generic_to_shared(p);
}
__device__ __forceinline__ void cp16(uint32_t dst, const void* src, int sz) {
    asm volatile("cp.async.ca.shared.global [%0], [%1], 16, %2;" :: "r"(dst), "l"(src), "r"(sz));
}
__device__ __forceinline__ void cp_commit() { asm volatile("cp.async.commit_group;"); }
template <int N> __device__ __forceinline__ void cp_wait() {
    asm volatile("cp.async.wait_group %0;" :: "n"(N));
}
__device__ __forceinline__ void mma_tf32(float (&c)[4], uint32_t a0, uint32_t a1, uint32_t a2,
                                         uint32_t a3, uint32_t b0, uint32_t b1) {
    asm("mma.sync.aligned.m16n8k8.row.col.f32.tf32.tf32.f32 "
        "{%0,%1,%2,%3},{%4,%5,%6,%7},{%8,%9},{%0,%1,%2,%3};"
        : "+f"(c[0]), "+f"(c[1]), "+f"(c[2]), "+f"(c[3])
        : "r"(a0), "r"(a1), "r"(a2), "r"(a3), "r"(b0), "r"(b1));
}

// GEMM tiling constants (shared by both tensor-core kernels)
#define WS_STR 264            // Ws row stride (k rows of 256 dout + 8 pad)  -> conflict-free B frags
#define XS_STR 20             // Xs row stride (n rows of 16 k + 4 pad)      -> conflict-free A frags
#define WS_STAGE (16 * WS_STR)
#define XS_STAGE (128 * XS_STR)
#define SMEM_UINTS (2 * WS_STAGE + 2 * XS_STAGE)
#define SMEM_BYTES (SMEM_UINTS * 4)

// ---------------- 1) per-stream global means over T ----------------
__global__ void means_kernel(const float* __restrict__ f0, const float* __restrict__ f1,
                             const float* __restrict__ f2, const float* __restrict__ f3) {
    int z = blockIdx.y;
    const float* f = (z == 0) ? f0 : (z == 1) ? f1 : (z == 2) ? f2 : f3;
    int T = (z < 2) ? 512 : 128;
    int idx = blockIdx.x * blockDim.x + threadIdx.x;
    if (idx >= BATCH * DDIM) return;
    float s0 = 0.f, s1 = 0.f, s2 = 0.f, s3 = 0.f;
    const float* p = f + idx;
    const int STRIDE = BATCH * DDIM;
    #pragma unroll 4
    for (int t = 0; t < T; t += 4) {
        s0 += p[(size_t)(t + 0) * STRIDE];
        s1 += p[(size_t)(t + 1) * STRIDE];
        s2 += p[(size_t)(t + 2) * STRIDE];
        s3 += p[(size_t)(t + 3) * STRIDE];
    }
    (&g_means[z][0][0])[idx] = ((s0 + s1) + (s2 + s3)) * (1.0f / (float)T);
}

// ---------------- 2) pair-gate MLPs ----------------
__global__ void mlp_kernel(const float* __restrict__ w1, const float* __restrict__ b1,
                           const float* __restrict__ w2, const float* __restrict__ b2) {
    __shared__ float vec[4][2048];
    __shared__ float red[4][256];
    int pi = blockIdx.x, bg = blockIdx.y;
    int i = c_api[pi], j = c_apj[pi];
    int p = i * 4 + j;
    int tid = threadIdx.x;
    for (int q = 0; q < 4; ++q) {
        int b = bg * 4 + q;
        for (int k = tid; k < 2048; k += 256)
            vec[q][k] = (k < 1024) ? g_means[i][b][k] : g_means[j][b][k - 1024];
    }
    __syncthreads();
    const float* w1p = w1 + (size_t)p * 2048 * 256 + tid;
    float a0 = 0.f, a1 = 0.f, a2 = 0.f, a3 = 0.f;
    #pragma unroll 4
    for (int k = 0; k < 2048; ++k) {
        float w = w1p[(size_t)k * 256];
        a0 = fmaf(vec[0][k], w, a0);
        a1 = fmaf(vec[1][k], w, a1);
        a2 = fmaf(vec[2][k], w, a2);
        a3 = fmaf(vec[3][k], w, a3);
    }
    float bb = b1[p * 256 + tid];
    float wv = w2[p * 256 + tid];
    red[0][tid] = fmaxf(a0 + bb, 0.f) * wv;
    red[1][tid] = fmaxf(a1 + bb, 0.f) * wv;
    red[2][tid] = fmaxf(a2 + bb, 0.f) * wv;
    red[3][tid] = fmaxf(a3 + bb, 0.f) * wv;
    __syncthreads();
    for (int s = 128; s > 0; s >>= 1) {
        if (tid < s) {
            red[0][tid] += red[0][tid + s];
            red[1][tid] += red[1][tid + s];
            red[2][tid] += red[2][tid + s];
            red[3][tid] += red[3][tid + s];
        }
        __syncthreads();
    }
    if (tid < 4) {
        float z = red[tid][0] + b2[p];
        g_score[p][bg * 4 + tid] = 1.f / (1.f + expf(-z));
    }
}

// ---------------- 3) resolve where-chains ----------------
__global__ void select_kernel() {
    int j = threadIdx.x >> 5;
    int lane = threadIdx.x & 31;
    int pA, pB, iA, iB;
    if (j < 2) { pA = 12 + j; iA = 3; pB = 8 + j; iB = 2; }
    else       { pA = 4 + j;  iA = 1; pB = j;     iB = 0; }
    float sA = g_score[pA][lane], sB = g_score[pB][lane];
    float mA = sA, mB = sB;
    #pragma unroll
    for (int o = 16; o > 0; o >>= 1) {
        mA += __shfl_xor_sync(0xffffffffu, mA, o);
        mB += __shfl_xor_sync(0xffffffffu, mB, o);
    }
    bool cA = (mA * (1.f / 32.f)) >= 0.3f;
    bool cB = (mB * (1.f / 32.f)) >= 0.3f;
    int sel = cA ? iA : (cB ? iB : -1);
    g_selscore[j][lane] = cA ? sA : (cB ? sB : 0.f);
    if (lane == 0) g_sel[j] = sel;
}

// ---------------- 4) repack weights: transpose + tf32-round ----------------
// Part A: g_wT2[slot][k=tap*1024+din][dout] = rna(f2s_w[widx][dout][din][tap])
// Part B: g_s2fT[din][dout] = rna(s2f_w[dout][din])
__global__ void repack_kernel(const float* __restrict__ f2s_w, const float* __restrict__ s2f_w) {
    long long idx = (long long)blockIdx.x * blockDim.x + threadIdx.x;
    const long long per_slot = 5LL * 1024 * 1024;
    if (idx < 2 * per_slot) {
        int slot = (int)(idx / per_slot);
        int sel = g_sel[slot + 2];
        if (sel < 0) return;
        int widx = sel * 2 + slot;
        long long r = idx - (long long)slot * per_slot;
        int k = (int)(r >> 10);
        int dout = (int)(r & 1023);
        int tap = k >> 10, din = k & 1023;
        g_wT2[slot][(size_t)k * 1024 + dout] =
            to_tf32(f2s_w[(((long long)widx * 1024 + dout) * 1024 + din) * 5 + tap]);
    } else {
        long long r = idx - 2 * per_slot;
        if (r >= 1024 * 1024) return;
        if (g_sel[0] < 0 && g_sel[1] < 0) return;
        int din = (int)(r >> 10), dout = (int)(r & 1023);
        g_s2fT[(size_t)din * 1024 + dout] = to_tf32(s2f_w[(size_t)dout * 1024 + din]);
    }
}

// ---------------- shared fragment-compute for one 16-K smem tile ----------------
// Ws: [16][WS_STR] rows k, cols dout(256); Xs: [128][XS_STR] rows n, cols k(16)
__device__ __forceinline__ void compute_tile(const uint32_t* __restrict__ ws,
                                             const uint32_t* __restrict__ xs,
                                             int wm, int wn, int grp, int tg,
                                             float (&acc)[2][8][4]) {
    #pragma unroll
    for (int ks = 0; ks < 2; ++ks) {
        int kb = ks * 8;
        uint32_t bf[8][2];
        #pragma unroll
        for (int ni = 0; ni < 8; ++ni) {
            int dd = wn * 64 + ni * 8 + grp;
            bf[ni][0] = ws[(kb + tg) * WS_STR + dd];
            bf[ni][1] = ws[(kb + tg + 4) * WS_STR + dd];
        }
        #pragma unroll
        for (int mi = 0; mi < 2; ++mi) {
            int nn = wm * 32 + mi * 16 + grp;
            uint32_t a0 = xs[nn * XS_STR + kb + tg];
            uint32_t a1 = xs[(nn + 8) * XS_STR + kb + tg];
            uint32_t a2 = xs[nn * XS_STR + kb + tg + 4];
            uint32_t a3 = xs[(nn + 8) * XS_STR + kb + tg + 4];
            #pragma unroll
            for (int ni = 0; ni < 8; ++ni)
                mma_tf32(acc[mi][ni], a0, a1, a2, a3, bf[ni][0], bf[ni][1]);
        }
    }
}

// ---------------- 5) s2f 1x1-conv GEMM (tensor core): y = X @ W^T + b ----------------
// M = n (4096 slow (t,b)), N = dout (1024), K = din (1024). 64 K-tiles.
__global__ __launch_bounds__(512, 1)
void s2f_tc(const float* __restrict__ f2, const float* __restrict__ f3,
            const float* __restrict__ bias) {
    int slot = blockIdx.z;
    int sel = g_sel[slot];
    if (sel < 0) return;
    const float* X = (sel == 3) ? f3 : f2;
    float* Y = g_y[slot];
    int n0 = blockIdx.x * 128, d0 = blockIdx.y * 256;
    extern __shared__ uint32_t dsm[];
    uint32_t* Ws = dsm;
    uint32_t* Xs = dsm + 2 * WS_STAGE;
    int tid = threadIdx.x;
    int wid = tid >> 5, lane = tid & 31;
    int wm = wid & 3, wn = wid >> 2;
    int grp = lane >> 2, tg = lane & 3;
    float acc[2][8][4];
    #pragma unroll
    for (int a = 0; a < 2; ++a)
        #pragma unroll
        for (int b = 0; b < 8; ++b)
            #pragma unroll
            for (int c = 0; c < 4; ++c) acc[a][b][c] = 0.f;

    // per-thread load geometry
    int r0 = tid >> 6, mc = tid & 63;              // W chunks: rows r0 and r0+8
    int xn = tid >> 2, xkg = tid & 3;              // X chunk: row xn, k-group xkg
    uint32_t wdst0 = smem_u32(Ws) + (uint32_t)(r0 * WS_STR + mc * 4) * 4;
    uint32_t wdst1 = wdst0 + (uint32_t)(8 * WS_STR) * 4;
    uint32_t xdst  = smem_u32(Xs) + (uint32_t)(xn * XS_STR + xkg * 4) * 4;
    const float* wsrc_base = g_s2fT + (size_t)r0 * 1024 + d0 + mc * 4;
    const float* xsrc_base = X + (size_t)(n0 + xn) * 1024 + xkg * 4;

    const int KT = 64;
    // prologue: stage 0
    {
        const float* w0 = wsrc_base;               // k rows 0..15
        cp16(wdst0, w0, 16);
        cp16(wdst1, w0 + 8 * 1024, 16);
        cp16(xdst, xsrc_base, 16);
        cp_commit();
    }
    for (int kt = 0; kt < KT; ++kt) {
        if (kt + 1 < KT) {
            int s = (kt + 1) & 1;
            const float* w0 = wsrc_base + (size_t)(kt + 1) * 16 * 1024;
            cp16(wdst0 + s * WS_STAGE * 4, w0, 16);
            cp16(wdst1 + s * WS_STAGE * 4, w0 + 8 * 1024, 16);
            cp16(xdst + s * XS_STAGE * 4, xsrc_base + (kt + 1) * 16, 16);
            cp_commit();
            cp_wait<1>();
        } else {
            cp_wait<0>();
        }
        __syncthreads();
        int s = kt & 1;
        compute_tile(Ws + s * WS_STAGE, Xs + s * XS_STAGE, wm, wn, grp, tg, acc);
        __syncthreads();
    }
    // epilogue: Y[n][d] = acc + bias[d]
    #pragma unroll
    for (int mi = 0; mi < 2; ++mi) {
        int r = n0 + wm * 32 + mi * 16 + grp;
        float* y0 = Y + (size_t)r * 1024 + d0 + wn * 64;
        float* y1 = Y + (size_t)(r + 8) * 1024 + d0 + wn * 64;
        #pragma unroll
        for (int ni = 0; ni < 8; ++ni) {
            int dd = ni * 8 + 2 * tg;
            float bz0 = bias[d0 + wn * 64 + dd];
            float bz1 = bias[d0 + wn * 64 + dd + 1];
            float2 v0 = make_float2(acc[mi][ni][0] + bz0, acc[mi][ni][1] + bz1);
            float2 v1 = make_float2(acc[mi][ni][2] + bz0, acc[mi][ni][3] + bz1);
            *(float2*)(y0 + dd) = v0;
            *(float2*)(y1 + dd) = v1;
        }
    }
}

// ---------------- 6) fast outputs: upsample + gated residual ----------------
__global__ void upsample_kernel(const float* __restrict__ f0, const float* __restrict__ f1,
                                float* __restrict__ out) {
    int slot = blockIdx.y;
    const float* FJ = slot ? f1 : f0;
    float* O = out + (size_t)slot * 16777216;
    int idx4 = blockIdx.x * blockDim.x + threadIdx.x;
    if (idx4 >= 512 * 32 * 256) return;
    float4 base = ((const float4*)FJ)[idx4];
    float4 res = base;
    int sel = g_sel[slot];
    if (sel >= 0) {
        int t = idx4 / (32 * 256);
        int rem = idx4 % (32 * 256);
        int b = rem >> 8;
        float s = g_selscore[slot][b];
        float srcp = (t + 0.5f) * 0.25f - 0.5f;
        srcp = fminf(fmaxf(srcp, 0.f), 127.f);
        int i0 = (int)floorf(srcp);
        int i1 = min(i0 + 1, 127);
        float wgt = srcp - (float)i0;
        const float4* yp = (const float4*)g_y[slot];
        float4 a = yp[i0 * (32 * 256) + rem];
        float4 c = yp[i1 * (32 * 256) + rem];
        res.x = base.x + s * ((1.f - wgt) * a.x + wgt * c.x);
        res.y = base.y + s * ((1.f - wgt) * a.y + wgt * c.y);
        res.z = base.z + s * ((1.f - wgt) * a.z + wgt * c.z);
        res.w = base.w + s * ((1.f - wgt) * a.w + wgt * c.w);
    }
    ((float4*)O)[idx4] = res;
}

// ---------------- 7) f2s strided-conv GEMM (tensor core) + gated residual ----------------
// M = n (4096 slow (t,b)), N = dout (1024), K = tap*1024+din (5120). 320 K-tiles.
__global__ __launch_bounds__(512, 1)
void f2s_tc(const float* __restrict__ f0, const float* __restrict__ f1,
            const float* __restrict__ f2, const float* __restrict__ f3,
            float* __restrict__ outbase) {
    int slot = blockIdx.z;
    int j = slot + 2;
    const float* FJ = (slot == 0) ? f2 : f3;
    float* O = outbase + ((slot == 0) ? (size_t)33554432 : (size_t)37748736);
    int n0 = blockIdx.x * 128, d0 = blockIdx.y * 256;
    int tid = threadIdx.x;
    int sel = g_sel[j];
    if (sel < 0) {                         // pass-through copy
        int c = tid & 63;
        for (int r = tid >> 6; r < 128; r += 8) {
            size_t off = (size_t)(n0 + r) * 1024 + d0;
            ((float4*)(O + off))[c] = ((const float4*)(FJ + off))[c];
        }
        return;
    }
    const float* X = (sel == 1) ? f1 : f0;  // [512][32][1024]
    extern __shared__ uint32_t dsm[];
    uint32_t* Ws = dsm;
    uint32_t* Xs = dsm + 2 * WS_STAGE;
    int wid = tid >> 5, lane = tid & 31;
    int wm = wid & 3, wn = wid >> 2;
    int grp = lane >> 2, tg = lane & 3;
    float acc[2][8][4];
    #pragma unroll
    for (int a = 0; a < 2; ++a)
        #pragma unroll
        for (int b = 0; b < 8; ++b)
            #pragma unroll
            for (int c = 0; c < 4; ++c) acc[a][b][c] = 0.f;

    int r0 = tid >> 6, mc = tid & 63;
    int xn = tid >> 2, xkg = tid & 3;
    uint32_t wdst0 = smem_u32(Ws) + (uint32_t)(r0 * WS_STR + mc * 4) * 4;
    uint32_t wdst1 = wdst0 + (uint32_t)(8 * WS_STR) * 4;
    uint32_t xdst  = smem_u32(Xs) + (uint32_t)(xn * XS_STR + xkg * 4) * 4;
    const float* wsrc_base = g_wT2[slot] + (size_t)r0 * 1024 + d0 + mc * 4;
    int nn_g = n0 + xn;
    int tfix = 4 * (nn_g >> 5) - 2;                 // + tap -> source time
    const float* xsrc_base = X + (size_t)(nn_g & 31) * 1024 + xkg * 4;

    const int KT = 320;
    {
        // kt = 0: tap = 0, din0 = 0
        cp16(wdst0, wsrc_base, 16);
        cp16(wdst1, wsrc_base + 8 * 1024, 16);
        int time = tfix;                            // tap 0
        const float* xs0 = (time >= 0) ? (xsrc_base + (size_t)time * 32768) : X;
        cp16(xdst, xs0, (time >= 0) ? 16 : 0);
        cp_commit();
    }
    for (int kt = 0; kt < KT; ++kt) {
        if (kt + 1 < KT) {
            int knext = kt + 1;
            int s = knext & 1;
            const float* w0 = wsrc_base + (size_t)knext * 16 * 1024;
            cp16(wdst0 + s * WS_STAGE * 4, w0, 16);
            cp16(wdst1 + s * WS_STAGE * 4, w0 + 8 * 1024, 16);
            int tap = knext >> 6;
            int din0 = (knext & 63) << 4;
            int time = tfix + tap;
            const float* xs0 = (time >= 0) ? (xsrc_base + (size_t)time * 32768 + din0) : X;
            cp16(xdst + s * XS_STAGE * 4, xs0, (time >= 0) ? 16 : 0);
            cp_commit();
            cp_wait<1>();
        } else {
            cp_wait<0>();
        }
        __syncthreads();
        int s = kt & 1;
        compute_tile(Ws + s * WS_STAGE, Xs + s * XS_STAGE, wm, wn, grp, tg, acc);
        __syncthreads();
    }
    // epilogue: O[n][d] = FJ[n][d] + score[b] * acc
    #pragma unroll
    for (int mi = 0; mi < 2; ++mi) {
        int r = n0 + wm * 32 + mi * 16 + grp;
        float s0 = g_selscore[j][r & 31];
        float s1 = g_selscore[j][(r + 8) & 31];
        const float* fp0 = FJ + (size_t)r * 1024 + d0 + wn * 64;
        const float* fp1 = FJ + (size_t)(r + 8) * 1024 + d0 + wn * 64;
        float* o0 = O + (size_t)r * 1024 + d0 + wn * 64;
        float* o1 = O + (size_t)(r + 8) * 1024 + d0 + wn * 64;
        #pragma unroll
        for (int ni = 0; ni < 8; ++ni) {
            int dd = ni * 8 + 2 * tg;
            float2 b0 = *(const float2*)(fp0 + dd);
            float2 b1 = *(const float2*)(fp1 + dd);
            float2 v0 = make_float2(b0.x + s0 * acc[mi][ni][0], b0.y + s0 * acc[mi][ni][1]);
            float2 v1 = make_float2(b1.x + s1 * acc[mi][ni][2], b1.y + s1 * acc[mi][ni][3]);
            *(float2*)(o0 + dd) = v0;
            *(float2*)(o1 + dd) = v1;
        }
    }
}

// ---------------- launch ----------------
extern "C" void kernel_launch(void* const* d_in, const int* in_sizes, int n_in,
                              void* d_out, int out_size) {
    (void)in_sizes; (void)n_in; (void)out_size;
    const float* f0 = (const float*)d_in[0];
    const float* f1 = (const float*)d_in[1];
    const float* f2 = (const float*)d_in[2];
    const float* f3 = (const float*)d_in[3];
    const float* w1 = (const float*)d_in[4];
    const float* b1 = (const float*)d_in[5];
    const float* w2 = (const float*)d_in[6];
    const float* b2 = (const float*)d_in[7];
    const float* s2f_w = (const float*)d_in[8];
    const float* s2f_b = (const float*)d_in[9];
    const float* f2s_w = (const float*)d_in[10];
    float* out = (float*)d_out;

    static bool attr_set = false;
    if (!attr_set) {
        cudaFuncSetAttribute(s2f_tc, cudaFuncAttributeMaxDynamicSharedMemorySize, SMEM_BYTES);
        cudaFuncSetAttribute(f2s_tc, cudaFuncAttributeMaxDynamicSharedMemorySize, SMEM_BYTES);
        attr_set = true;
    }

    means_kernel<<<dim3(128, 4), 256>>>(f0, f1, f2, f3);
    mlp_kernel<<<dim3(8, 8), 256>>>(w1, b1, w2, b2);
    select_kernel<<<1, 128>>>();
    repack_kernel<<<45056, 256>>>(f2s_w, s2f_w);
    s2f_tc<<<dim3(32, 4, 2), 512, SMEM_BYTES>>>(f2, f3, s2f_b);
    upsample_kernel<<<dim3(16384, 2), 256>>>(f0, f1, out);
    f2s_tc<<<dim3(32, 4, 2), 512, SMEM_BYTES>>>(f0, f1, f2, f3, out);
}